// round 14
// baseline (speedup 1.0000x reference)
#include <cuda_runtime.h>
#include <stdint.h>

// Shape fixed for this dataset: B=512 rows, N=16384 residues/row, A atoms/row.
#define N_RES    16384
#define TPB      384
#define NG4      (N_RES / 4)     // 4096 build groups (4 residues each)
#define NU4      (N_RES / 8)     // 2048 uint4 groups of 8 key16s
#define HBINS    2048            // histogram on key bits 31..21
#define CAP      6144            // bin-member compaction capacity
#define RCAP     2048            // ==T16 resolve capacity (aliases hist)
// dynamic smem: key16 32KB | hist/cand_key 8KB | cand_idx 12KB = 53248 B
#define SMEM_BYTES (32768 + 8192 + 12288)

// Order-preserving float->uint transform (total order == IEEE float compare).
__device__ __forceinline__ unsigned int f2key(float f) {
    unsigned int u = __float_as_uint(f);
    return u ^ ((u & 0x80000000u) ? 0xFFFFFFFFu : 0x80000000u);
}

// Exact replica of reference arithmetic (RN, no FMA contraction).
__device__ __forceinline__ unsigned int dist_key(float cx, float cy, float cz,
                                                 float px, float py, float pz,
                                                 float m) {
    float dx = __fsub_rn(cx, px);
    float dy = __fsub_rn(cy, py);
    float dz = __fsub_rn(cz, pz);
    float ss = __fadd_rn(__fadd_rn(__fmul_rn(dx, dx), __fmul_rn(dy, dy)),
                         __fmul_rn(dz, dz));
    float d = __fsqrt_rn(__fadd_rn(ss, 1e-12f));
    d = __fadd_rn(d, __fmul_rn(__fsub_rn(1.0f, m), 1.0e10f));
    return f2key(d);
}

__device__ __forceinline__ void hist_add(unsigned int* hist, unsigned int bin) {
    unsigned int peers = __match_any_sync(0xFFFFFFFFu, bin);
    int leader = __ffs(peers) - 1;
    if ((threadIdx.x & 31) == leader) atomicAdd(&hist[bin], __popc(peers));
}

__global__ void __launch_bounds__(TPB, 4)
spatial_mask_kernel(const float* __restrict__ ca,      // [B, N, 3]
                    const float* __restrict__ rmask,   // [B, N]
                    const float* __restrict__ apos,    // [B, A, 3]
                    const float* __restrict__ amask,   // [B, A]
                    const int*   __restrict__ topk_ptr,
                    int A,
                    float* __restrict__ out0,          // [B, N]
                    float* __restrict__ out1)          // [B, N]
{
    extern __shared__ unsigned char sm[];
    unsigned short* key16    = reinterpret_cast<unsigned short*>(sm);        // [16384]
    unsigned int*   hist     = reinterpret_cast<unsigned int*>(sm + 32768);  // [2048]
    unsigned int*   cand_key = reinterpret_cast<unsigned int*>(sm + 32768);  // alias post-scan
    unsigned short* cand_idx = reinterpret_cast<unsigned short*>(sm + 40960);// [6144]

    __shared__ float s_cx, s_cy, s_cz;
    __shared__ int s_k;
    __shared__ unsigned int s_wsum[8];
    __shared__ unsigned int s_sub[32];
    __shared__ int s_b11, s_cb11;
    __shared__ unsigned int s_T16;
    __shared__ int s_cb, s_gsz, s_nc, s_cnt;

    const int b = blockIdx.x;
    const int t = threadIdx.x;
    const int lane = t & 31;
    const size_t row = (size_t)b * N_RES;

    for (int i = t; i < HBINS; i += TPB) hist[i] = 0;
    if (t < 32) s_sub[t] = 0;
    if (t == 32) s_nc = 0;
    if (t == 33) s_cnt = 0;
    if (t == 34) { s_b11 = 0; s_cb11 = 0; }

    // ---- centroid: strict sequential f32 sum in atom order.
    if (t == 0) {
        const float* ap = apos + (size_t)b * A * 3;
        const float* am = amask + (size_t)b * A;
        float sx = 0.f, sy = 0.f, sz = 0.f, smm = 0.f;
        #pragma unroll 4
        for (int a = 0; a < A; ++a) {
            sx  = __fadd_rn(sx,  ap[a * 3 + 0]);
            sy  = __fadd_rn(sy,  ap[a * 3 + 1]);
            sz  = __fadd_rn(sz,  ap[a * 3 + 2]);
            smm = __fadd_rn(smm, am[a]);
        }
        s_cx = __fdiv_rn(sx, smm);
        s_cy = __fdiv_rn(sy, smm);
        s_cz = __fdiv_rn(sz, smm);
        s_k  = *topk_ptr;
    }
    __syncthreads();
    const float cx = s_cx, cy = s_cy, cz = s_cz;
    const int kk = s_k;
    const bool normalK = (kk > 0 && kk < N_RES);

    // ---- PASS 1 (build): distances -> key16 in SMEM + inline coarse hist.
    //      ca is single-use: evict-first loads (__ldcs).
    const float4* ca4 = reinterpret_cast<const float4*>(ca + row * 3);
    const float4* rm4 = reinterpret_cast<const float4*>(rmask + row);
    uint2* key16v = reinterpret_cast<uint2*>(key16);
    #pragma unroll 4
    for (int g = t; g < NG4; g += TPB) {
        float4 v0 = __ldcs(&ca4[g * 3 + 0]);
        float4 v1 = __ldcs(&ca4[g * 3 + 1]);
        float4 v2 = __ldcs(&ca4[g * 3 + 2]);
        float4 m  = rm4[g];
        unsigned int k0 = dist_key(cx, cy, cz, v0.x, v0.y, v0.z, m.x);
        unsigned int k1 = dist_key(cx, cy, cz, v0.w, v1.x, v1.y, m.y);
        unsigned int k2 = dist_key(cx, cy, cz, v1.z, v1.w, v2.x, m.z);
        unsigned int k3 = dist_key(cx, cy, cz, v2.y, v2.z, v2.w, m.w);
        uint2 packed;
        packed.x = (k0 >> 16) | (k1 & 0xFFFF0000u);
        packed.y = (k2 >> 16) | (k3 & 0xFFFF0000u);
        key16v[g] = packed;
        if (normalK) {
            hist_add(hist, k0 >> 21);
            hist_add(hist, k1 >> 21);
            hist_add(hist, k2 >> 21);
            hist_add(hist, k3 >> 21);
        }
    }
    __syncthreads();

    // ---- hist scan: 11-bit bin containing the k-th key.
    int b11s;
    if (normalK) {
        const int w = t >> 5;
        unsigned int hh[8];
        unsigned int local = 0, incl = 0;
        if (t < 256) {
            uint4 h0 = reinterpret_cast<uint4*>(hist)[t * 2];
            uint4 h1 = reinterpret_cast<uint4*>(hist)[t * 2 + 1];
            hh[0]=h0.x; hh[1]=h0.y; hh[2]=h0.z; hh[3]=h0.w;
            hh[4]=h1.x; hh[5]=h1.y; hh[6]=h1.z; hh[7]=h1.w;
            #pragma unroll
            for (int j = 0; j < 8; ++j) local += hh[j];
            incl = local;
            #pragma unroll
            for (int o = 1; o < 32; o <<= 1) {
                unsigned int v = __shfl_up_sync(0xFFFFFFFFu, incl, o);
                if (lane >= o) incl += v;
            }
            if (lane == 31) s_wsum[w] = incl;
        }
        __syncthreads();
        if (t < 256) {
            unsigned int pw = 0;
            for (int j = 0; j < w; ++j) pw += s_wsum[j];
            unsigned int pre = pw + incl - local;   // exclusive prefix
            if ((int)pre < kk && (int)(pre + local) >= kk) {
                unsigned int cum = pre;
                #pragma unroll
                for (int j = 0; j < 8; ++j) {
                    if ((int)(cum + hh[j]) >= kk) { s_b11 = t * 8 + j; s_cb11 = (int)cum; break; }
                    cum += hh[j];
                }
            }
        }
        __syncthreads();
        b11s = s_b11;
    } else {
        b11s = (kk >= N_RES) ? (int)HBINS : -1;   // all / none
    }

    // ---- PASS 2 (fused): tentative WRITE + SPARSE compaction of bin members.
    //      Tentative rule: selected <=> (key16>>5) <= b11 (whole bin provisionally
    //      selected; fixed up below). NO convergent ops in this loop.
    const uint4* kvv = reinterpret_cast<const uint4*>(key16);
    float4* o0 = reinterpret_cast<float4*>(out0 + row);
    float4* o1 = reinterpret_cast<float4*>(out1 + row);
    #pragma unroll 2
    for (int q = t; q < NU4; q += TPB) {
        uint4 v = kvv[q];
        unsigned int xs[8] = {v.x & 0xFFFFu, v.x >> 16, v.y & 0xFFFFu, v.y >> 16,
                              v.z & 0xFFFFu, v.z >> 16, v.w & 0xFFFFu, v.w >> 16};
        float4 m0 = rm4[q * 2 + 0];
        float4 m1 = rm4[q * 2 + 1];
        bool s0 = ((int)(xs[0] >> 5) <= b11s), s1 = ((int)(xs[1] >> 5) <= b11s);
        bool s2 = ((int)(xs[2] >> 5) <= b11s), s3 = ((int)(xs[3] >> 5) <= b11s);
        bool s4 = ((int)(xs[4] >> 5) <= b11s), s5 = ((int)(xs[5] >> 5) <= b11s);
        bool s6 = ((int)(xs[6] >> 5) <= b11s), s7 = ((int)(xs[7] >> 5) <= b11s);
        float4 a0, a1, c0, c1;
        a0.x = s0 ? 0.0f : m0.x;  a0.y = s1 ? 0.0f : m0.y;
        a0.z = s2 ? 0.0f : m0.z;  a0.w = s3 ? 0.0f : m0.w;
        a1.x = s4 ? 0.0f : m1.x;  a1.y = s5 ? 0.0f : m1.y;
        a1.z = s6 ? 0.0f : m1.z;  a1.w = s7 ? 0.0f : m1.w;
        c0.x = s0 ? 32.0f : __fsub_rn(1.0f, m0.x);
        c0.y = s1 ? 32.0f : __fsub_rn(1.0f, m0.y);
        c0.z = s2 ? 32.0f : __fsub_rn(1.0f, m0.z);
        c0.w = s3 ? 32.0f : __fsub_rn(1.0f, m0.w);
        c1.x = s4 ? 32.0f : __fsub_rn(1.0f, m1.x);
        c1.y = s5 ? 32.0f : __fsub_rn(1.0f, m1.y);
        c1.z = s6 ? 32.0f : __fsub_rn(1.0f, m1.z);
        c1.w = s7 ? 32.0f : __fsub_rn(1.0f, m1.w);
        __stcs(&o0[q * 2 + 0], a0);
        __stcs(&o0[q * 2 + 1], a1);
        __stcs(&o1[q * 2 + 0], c0);
        __stcs(&o1[q * 2 + 1], c1);

        // sparse compaction: plain predicated atomic (members are ~1-3%)
        #pragma unroll
        for (int j = 0; j < 8; ++j) {
            if ((int)(xs[j] >> 5) == b11s) {
                int pos = atomicAdd(&s_nc, 1);
                if (pos < CAP) cand_idx[pos] = (unsigned short)(q * 8 + j);
            }
        }
    }
    if (!normalK) return;   // outputs final (block-uniform exit)
    __syncthreads();

    const int nc = s_nc;
    if (nc <= CAP) {
        // ---- sub-histogram over the compact list (O(nc), 5 low bits)
        for (int i = t; i < nc; i += TPB)
            atomicAdd(&s_sub[key16[cand_idx[i]] & 31u], 1u);
        __syncthreads();
        if (t == 0) {
            int cum = s_cb11;
            #pragma unroll
            for (int j = 0; j < 32; ++j) {
                int h = (int)s_sub[j];
                if (cum + h >= kk) {
                    s_T16 = ((unsigned int)s_b11 << 5) | (unsigned int)j;
                    s_cb = cum;
                    s_gsz = h;
                    break;
                }
                cum += h;
            }
        }
        __syncthreads();
        const unsigned int T16 = s_T16;
        const int krem = kk - s_cb;
        const int gsz = s_gsz;

        // ---- fix-up: bin members with key16 > T16 -> rewrite unselected.
        for (int i = t; i < nc; i += TPB) {
            int n = cand_idx[i];
            if (key16[n] > T16) {
                float mv = __ldg(rmask + row + n);
                out0[row + n] = mv;
                out1[row + n] = __fsub_rn(1.0f, mv);
            }
        }
        __syncthreads();

        if (krem < gsz && gsz <= RCAP) {
            // ---- warp 0: resolve ==T16 group at full precision; rewrite
            //      excluded entries (index-stable ties).
            if (t < 32) {
                int m = 0;
                for (int base = 0; base < nc; base += 32) {
                    int i = base + lane;
                    unsigned short idx = 0;
                    bool p = false;
                    if (i < nc) {
                        idx = cand_idx[i];
                        p = (key16[idx] == T16);
                    }
                    unsigned int bal = __ballot_sync(0xFFFFFFFFu, p);
                    int rank = __popc(bal & ((1u << lane) - 1u));
                    if (p) {
                        int n = (int)idx;
                        float px = __ldg(ca + (row + n) * 3 + 0);
                        float py = __ldg(ca + (row + n) * 3 + 1);
                        float pz = __ldg(ca + (row + n) * 3 + 2);
                        float mm = __ldg(rmask + row + n);
                        cand_key[m + rank] = dist_key(cx, cy, cz, px, py, pz, mm);
                        cand_idx[m + rank] = idx;   // in-place: m+rank <= base+lane
                    }
                    m += __popc(bal);
                    __syncwarp();
                }
                unsigned int P = T16 << 16;
                for (int bit = 15; bit >= 0; --bit) {
                    unsigned int C = P | (1u << bit);
                    int c = 0;
                    for (int i = lane; i < m; i += 32) c += (cand_key[i] < C);
                    c = __reduce_add_sync(0xFFFFFFFFu, c);
                    if (c < krem) P = C;
                }
                int cb2 = 0;
                for (int i = lane; i < m; i += 32) cb2 += (cand_key[i] < P);
                cb2 = __reduce_add_sync(0xFFFFFFFFu, cb2);
                const int req = krem - cb2;   // # of ==P keys kept (lowest index)
                for (int i = lane; i < m; i += 32) {
                    unsigned int x = cand_key[i];
                    bool excl = false;
                    if (x > P) excl = true;
                    else if (x == P) {
                        int rk = 0;
                        unsigned short my = cand_idx[i];
                        for (int j2 = 0; j2 < m; ++j2)
                            rk += (cand_key[j2] == P && cand_idx[j2] < my);
                        excl = (rk >= req);
                    }
                    if (excl) {
                        int n = cand_idx[i];
                        float mv = __ldg(rmask + row + n);
                        out0[row + n] = mv;
                        out1[row + n] = __fsub_rn(1.0f, mv);
                    }
                }
            }
        } else if (krem < gsz) {
            // gsz > RCAP (pathological): t0-serial exact resolve over ==T16.
            if (t == 0) {
                unsigned int P = T16 << 16;
                for (int bit = 15; bit >= 0; --bit) {
                    unsigned int C = P | (1u << bit);
                    int c = 0;
                    for (int i = 0; i < nc; ++i) {
                        int n = cand_idx[i];
                        if (key16[n] == T16) {
                            float px = ca[(row + n) * 3 + 0];
                            float py = ca[(row + n) * 3 + 1];
                            float pz = ca[(row + n) * 3 + 2];
                            float mm = rmask[row + n];
                            c += (dist_key(cx, cy, cz, px, py, pz, mm) < C);
                        }
                    }
                    if (c < krem) P = C;
                }
                int cb2 = 0;
                for (int i = 0; i < nc; ++i) {
                    int n = cand_idx[i];
                    if (key16[n] == T16) {
                        float px = ca[(row + n) * 3 + 0];
                        float py = ca[(row + n) * 3 + 1];
                        float pz = ca[(row + n) * 3 + 2];
                        float mm = rmask[row + n];
                        cb2 += (dist_key(cx, cy, cz, px, py, pz, mm) < P);
                    }
                }
                int req = krem - cb2, seen = 0;
                for (int n = 0; n < N_RES; ++n) {
                    if (key16[n] == T16) {
                        float px = ca[(row + n) * 3 + 0];
                        float py = ca[(row + n) * 3 + 1];
                        float pz = ca[(row + n) * 3 + 2];
                        float mm = rmask[row + n];
                        unsigned int x = dist_key(cx, cy, cz, px, py, pz, mm);
                        bool excl = (x > P);
                        if (x == P) {
                            ++seen;
                            excl = (seen > req);
                        }
                        if (excl) {
                            out0[row + n] = mm;
                            out1[row + n] = __fsub_rn(1.0f, mm);
                        }
                    }
                }
            }
        }
    } else {
        // ---- cand overflow (effectively never): full-pass exact fix-up.
        const unsigned int b11f = (unsigned int)b11s;
        // sub-hist from full array
        for (int n = t; n < N_RES; n += TPB) {
            unsigned int x = key16[n];
            if ((x >> 5) == b11f) atomicAdd(&s_sub[x & 31u], 1u);
        }
        __syncthreads();
        if (t == 0) {
            int cum = s_cb11;
            #pragma unroll
            for (int j = 0; j < 32; ++j) {
                int h = (int)s_sub[j];
                if (cum + h >= kk) {
                    s_T16 = ((unsigned int)s_b11 << 5) | (unsigned int)j;
                    s_cb = cum;
                    s_gsz = h;
                    break;
                }
                cum += h;
            }
        }
        __syncthreads();
        const unsigned int T16 = s_T16;
        const int krem = kk - s_cb;
        const int gsz = s_gsz;
        for (int n = t; n < N_RES; n += TPB) {
            unsigned int x = key16[n];
            if ((x >> 5) == b11f && x > T16) {
                float mv = __ldg(rmask + row + n);
                out0[row + n] = mv;
                out1[row + n] = __fsub_rn(1.0f, mv);
            }
        }
        __syncthreads();
        if (krem < gsz) {
            // block-parallel bitwise search over ==T16 (recompute full keys)
            unsigned int P = T16 << 16;
            for (int bit = 15; bit >= 0; --bit) {
                if (t == 0) s_cnt = 0;
                __syncthreads();
                unsigned int C = P | (1u << bit);
                int c = 0;
                for (int n = t; n < N_RES; n += TPB) {
                    if (key16[n] == T16) {
                        float px = __ldg(ca + (row + n) * 3 + 0);
                        float py = __ldg(ca + (row + n) * 3 + 1);
                        float pz = __ldg(ca + (row + n) * 3 + 2);
                        float mm = __ldg(rmask + row + n);
                        c += (dist_key(cx, cy, cz, px, py, pz, mm) < C);
                    }
                }
                c = __reduce_add_sync(0xFFFFFFFFu, c);
                if ((t & 31) == 0) atomicAdd(&s_cnt, c);
                __syncthreads();
                if (s_cnt < krem) P = C;
                __syncthreads();
            }
            if (t == 0) s_cnt = 0;
            __syncthreads();
            int cb2 = 0;
            for (int n = t; n < N_RES; n += TPB) {
                if (key16[n] == T16) {
                    float px = __ldg(ca + (row + n) * 3 + 0);
                    float py = __ldg(ca + (row + n) * 3 + 1);
                    float pz = __ldg(ca + (row + n) * 3 + 2);
                    float mm = __ldg(rmask + row + n);
                    unsigned int x = dist_key(cx, cy, cz, px, py, pz, mm);
                    if (x > P) {
                        out0[row + n] = mm;
                        out1[row + n] = __fsub_rn(1.0f, mm);
                    } else if (x < P) {
                        cb2 += 1;
                    }
                }
            }
            cb2 = __reduce_add_sync(0xFFFFFFFFu, cb2);
            if ((t & 31) == 0) atomicAdd(&s_cnt, cb2);
            __syncthreads();
            if (t == 0) {
                const int req = krem - s_cnt;
                int seen = 0;
                for (int n = 0; n < N_RES; ++n) {
                    if (key16[n] == T16) {
                        float px = ca[(row + n) * 3 + 0];
                        float py = ca[(row + n) * 3 + 1];
                        float pz = ca[(row + n) * 3 + 2];
                        float mm = rmask[row + n];
                        unsigned int x = dist_key(cx, cy, cz, px, py, pz, mm);
                        if (x == P) {
                            ++seen;
                            if (seen > req) {
                                out0[row + n] = mm;
                                out1[row + n] = __fsub_rn(1.0f, mm);
                            }
                        }
                    }
                }
            }
        }
    }
}

extern "C" void kernel_launch(void* const* d_in, const int* in_sizes, int n_in,
                              void* d_out, int out_size) {
    const float* ca    = (const float*)d_in[0];
    const float* rmask = (const float*)d_in[1];
    const float* apos  = (const float*)d_in[2];
    const float* amask = (const float*)d_in[3];
    const int*   topk  = (const int*)d_in[5];   // [ca, rmask, apos, amask, max_p, top_k]

    const int BN = in_sizes[1];          // B * N
    const int B  = BN / N_RES;
    const int A  = (B > 0) ? in_sizes[3] / B : 64;

    float* out0 = (float*)d_out;
    float* out1 = out0 + (size_t)BN;

    cudaFuncSetAttribute(spatial_mask_kernel,
                         cudaFuncAttributeMaxDynamicSharedMemorySize, SMEM_BYTES);
    spatial_mask_kernel<<<B, TPB, SMEM_BYTES>>>(ca, rmask, apos, amask, topk, A,
                                                out0, out1);
}

// round 15
// speedup vs baseline: 1.0440x; 1.0440x over previous
#include <cuda_runtime.h>
#include <stdint.h>

// Shape fixed for this dataset: B=512 rows, N=16384 residues/row, A atoms/row.
#define N_RES    16384
#define TPB      384
#define NG4      (N_RES / 4)     // 4096 build groups (4 residues each)
#define NU4      (N_RES / 8)     // 2048 uint4 groups of 8 key16s
#define HBINS    2048            // histogram on key bits 31..21
#define CAP      4096            // bin-member compaction capacity
#define RCAP     2048            // ==T16 resolve capacity (cand_key aliases hist)
// dynamic smem: key16 32KB | hist/cand_key 8KB | cand_idx 8KB = 48KB
#define SMEM_BYTES (32768 + 8192 + 8192)

// Order-preserving float->uint transform (total order == IEEE float compare).
__device__ __forceinline__ unsigned int f2key(float f) {
    unsigned int u = __float_as_uint(f);
    return u ^ ((u & 0x80000000u) ? 0xFFFFFFFFu : 0x80000000u);
}

// Exact replica of reference arithmetic (RN, no FMA contraction).
__device__ __forceinline__ unsigned int dist_key(float cx, float cy, float cz,
                                                 float px, float py, float pz,
                                                 float m) {
    float dx = __fsub_rn(cx, px);
    float dy = __fsub_rn(cy, py);
    float dz = __fsub_rn(cz, pz);
    float ss = __fadd_rn(__fadd_rn(__fmul_rn(dx, dx), __fmul_rn(dy, dy)),
                         __fmul_rn(dz, dz));
    float d = __fsqrt_rn(__fadd_rn(ss, 1e-12f));
    d = __fadd_rn(d, __fmul_rn(__fsub_rn(1.0f, m), 1.0e10f));
    return f2key(d);
}

__device__ __forceinline__ void hist_add(unsigned int* hist, unsigned int bin) {
    unsigned int peers = __match_any_sync(0xFFFFFFFFu, bin);
    int leader = __ffs(peers) - 1;
    if ((threadIdx.x & 31) == leader) atomicAdd(&hist[bin], __popc(peers));
}

__global__ void __launch_bounds__(TPB, 4)
spatial_mask_kernel(const float* __restrict__ ca,      // [B, N, 3]
                    const float* __restrict__ rmask,   // [B, N]
                    const float* __restrict__ apos,    // [B, A, 3]
                    const float* __restrict__ amask,   // [B, A]
                    const int*   __restrict__ topk_ptr,
                    int A,
                    float* __restrict__ out0,          // [B, N]
                    float* __restrict__ out1)          // [B, N]
{
    extern __shared__ unsigned char sm[];
    unsigned short* key16    = reinterpret_cast<unsigned short*>(sm);        // [16384]
    unsigned int*   hist     = reinterpret_cast<unsigned int*>(sm + 32768);  // [2048]
    unsigned int*   cand_key = reinterpret_cast<unsigned int*>(sm + 32768);  // alias post-scan
    unsigned short* cand_idx = reinterpret_cast<unsigned short*>(sm + 40960);// [4096]

    __shared__ float s_cx, s_cy, s_cz;
    __shared__ int s_k;
    __shared__ unsigned int s_wsum[8];
    __shared__ unsigned int s_sub[32];
    __shared__ int s_b11, s_cb11;
    __shared__ unsigned int s_T16;
    __shared__ int s_cb, s_gsz, s_nc, s_cnt;

    const int b = blockIdx.x;
    const int t = threadIdx.x;
    const int lane = t & 31;
    const size_t row = (size_t)b * N_RES;

    for (int i = t; i < HBINS; i += TPB) hist[i] = 0;
    if (t < 32) s_sub[t] = 0;
    if (t == 32) s_nc = 0;
    if (t == 33) s_cnt = 0;
    if (t == 34) { s_b11 = 0; s_cb11 = 0; }

    // ---- centroid: strict sequential f32 sum in atom order.
    if (t == 0) {
        const float* ap = apos + (size_t)b * A * 3;
        const float* am = amask + (size_t)b * A;
        float sx = 0.f, sy = 0.f, sz = 0.f, smm = 0.f;
        #pragma unroll 4
        for (int a = 0; a < A; ++a) {
            sx  = __fadd_rn(sx,  ap[a * 3 + 0]);
            sy  = __fadd_rn(sy,  ap[a * 3 + 1]);
            sz  = __fadd_rn(sz,  ap[a * 3 + 2]);
            smm = __fadd_rn(smm, am[a]);
        }
        s_cx = __fdiv_rn(sx, smm);
        s_cy = __fdiv_rn(sy, smm);
        s_cz = __fdiv_rn(sz, smm);
        s_k  = *topk_ptr;
    }
    __syncthreads();
    const float cx = s_cx, cy = s_cy, cz = s_cz;
    const int kk = s_k;
    const bool normalK = (kk > 0 && kk < N_RES);

    // ---- build: distances -> key16 in SMEM + inline coarse histogram.
    //      ca is single-use: evict-first loads (__ldcs).
    const float4* ca4 = reinterpret_cast<const float4*>(ca + row * 3);
    const float4* rm4 = reinterpret_cast<const float4*>(rmask + row);
    uint2* key16v = reinterpret_cast<uint2*>(key16);
    #pragma unroll 4
    for (int g = t; g < NG4; g += TPB) {
        float4 v0 = __ldcs(&ca4[g * 3 + 0]);
        float4 v1 = __ldcs(&ca4[g * 3 + 1]);
        float4 v2 = __ldcs(&ca4[g * 3 + 2]);
        float4 m  = rm4[g];
        unsigned int k0 = dist_key(cx, cy, cz, v0.x, v0.y, v0.z, m.x);
        unsigned int k1 = dist_key(cx, cy, cz, v0.w, v1.x, v1.y, m.y);
        unsigned int k2 = dist_key(cx, cy, cz, v1.z, v1.w, v2.x, m.z);
        unsigned int k3 = dist_key(cx, cy, cz, v2.y, v2.z, v2.w, m.w);
        uint2 packed;
        packed.x = (k0 >> 16) | (k1 & 0xFFFF0000u);
        packed.y = (k2 >> 16) | (k3 & 0xFFFF0000u);
        key16v[g] = packed;
        if (normalK) {
            hist_add(hist, k0 >> 21);
            hist_add(hist, k1 >> 21);
            hist_add(hist, k2 >> 21);
            hist_add(hist, k3 >> 21);
        }
    }
    __syncthreads();

    if (normalK) {
        // ---- scan 2048-bin histogram: find 11-bit bin containing the k-th key
        {
            const int w = t >> 5;
            unsigned int hh[8];
            unsigned int local = 0, incl = 0;
            if (t < 256) {
                uint4 h0 = reinterpret_cast<uint4*>(hist)[t * 2];
                uint4 h1 = reinterpret_cast<uint4*>(hist)[t * 2 + 1];
                hh[0]=h0.x; hh[1]=h0.y; hh[2]=h0.z; hh[3]=h0.w;
                hh[4]=h1.x; hh[5]=h1.y; hh[6]=h1.z; hh[7]=h1.w;
                #pragma unroll
                for (int j = 0; j < 8; ++j) local += hh[j];
                incl = local;
                #pragma unroll
                for (int o = 1; o < 32; o <<= 1) {
                    unsigned int v = __shfl_up_sync(0xFFFFFFFFu, incl, o);
                    if (lane >= o) incl += v;
                }
                if (lane == 31) s_wsum[w] = incl;
            }
            __syncthreads();
            if (t < 256) {
                unsigned int pw = 0;
                for (int j = 0; j < w; ++j) pw += s_wsum[j];
                unsigned int pre = pw + incl - local;   // exclusive prefix
                if ((int)pre < kk && (int)(pre + local) >= kk) {
                    unsigned int cum = pre;
                    #pragma unroll
                    for (int j = 0; j < 8; ++j) {
                        if ((int)(cum + hh[j]) >= kk) { s_b11 = t * 8 + j; s_cb11 = (int)cum; break; }
                        cum += hh[j];
                    }
                }
            }
            __syncthreads();
        }

        // ---- FUSED sparse pass: sub-histogram (5 low bits) + compaction of
        //      the chosen bin's members. Plain predicated atomics only —
        //      members are ~1-3% of elements, no convergence machinery.
        {
            const unsigned int b11 = (unsigned int)s_b11;
            const uint4* kv = reinterpret_cast<const uint4*>(key16);
            #pragma unroll 2
            for (int q = t; q < NU4; q += TPB) {
                uint4 v = kv[q];
                unsigned int xs[8] = {v.x & 0xFFFFu, v.x >> 16, v.y & 0xFFFFu, v.y >> 16,
                                      v.z & 0xFFFFu, v.z >> 16, v.w & 0xFFFFu, v.w >> 16};
                #pragma unroll
                for (int j = 0; j < 8; ++j) {
                    if ((xs[j] >> 5) == b11) {
                        atomicAdd(&s_sub[xs[j] & 31u], 1u);
                        int pos = atomicAdd(&s_nc, 1);
                        if (pos < CAP) cand_idx[pos] = (unsigned short)(q * 8 + j);
                    }
                }
            }
            __syncthreads();
            if (t == 0) {
                int cum = s_cb11;
                #pragma unroll
                for (int j = 0; j < 32; ++j) {
                    int h = (int)s_sub[j];
                    if (cum + h >= kk) {
                        s_T16 = ((unsigned int)s_b11 << 5) | (unsigned int)j;
                        s_cb = cum;
                        s_gsz = h;
                        break;
                    }
                    cum += h;
                }
            }
            __syncthreads();
        }

        const unsigned int T16 = s_T16;
        const int krem = kk - s_cb;
        const bool need_resolve = (krem < s_gsz);
        const int nc = s_nc;

        if (need_resolve) {
            if (nc <= CAP && s_gsz <= RCAP) {
                // ---- warp 0: filter cand list for ==T16 (warp-local compaction
                //      over only nc entries), recompute full keys, resolve low
                //      16 bits, mark dropped entries in key16.
                if (t < 32) {
                    int m = 0;
                    for (int base = 0; base < nc; base += 32) {
                        int i = base + lane;
                        unsigned short idx = 0;
                        bool p = false;
                        if (i < nc) {
                            idx = cand_idx[i];
                            p = (key16[idx] == T16);
                        }
                        unsigned int bal = __ballot_sync(0xFFFFFFFFu, p);
                        int rank = __popc(bal & ((1u << lane) - 1u));
                        if (p) {
                            int n = (int)idx;
                            float px = __ldg(ca + (row + n) * 3 + 0);
                            float py = __ldg(ca + (row + n) * 3 + 1);
                            float pz = __ldg(ca + (row + n) * 3 + 2);
                            float mm = __ldg(rmask + row + n);
                            cand_key[m + rank] = dist_key(cx, cy, cz, px, py, pz, mm);
                            cand_idx[m + rank] = idx;   // in-place: m+rank <= base+lane
                        }
                        m += __popc(bal);
                        __syncwarp();
                    }
                    unsigned int P = T16 << 16;
                    for (int bit = 15; bit >= 0; --bit) {
                        unsigned int C = P | (1u << bit);
                        int c = 0;
                        for (int i = lane; i < m; i += 32) c += (cand_key[i] < C);
                        c = __reduce_add_sync(0xFFFFFFFFu, c);
                        if (c < krem) P = C;
                    }
                    int cb2 = 0;
                    for (int i = lane; i < m; i += 32) cb2 += (cand_key[i] < P);
                    cb2 = __reduce_add_sync(0xFFFFFFFFu, cb2);
                    const int req = krem - cb2;   // # of ==P keys kept (lowest index)
                    for (int i = lane; i < m; i += 32) {
                        unsigned int x = cand_key[i];
                        bool sel;
                        if (x < P) sel = true;
                        else if (x > P) sel = false;
                        else {
                            int rk = 0;
                            unsigned short my = cand_idx[i];
                            for (int j2 = 0; j2 < m; ++j2)
                                rk += (cand_key[j2] == P && cand_idx[j2] < my);
                            sel = (rk < req);   // lowest-index ties kept (top_k stable)
                        }
                        if (!sel) key16[cand_idx[i]] = (unsigned short)0xFFFFu;
                    }
                }
            } else {
                // ---- fallback (capacity overflow; effectively never taken): exact,
                //      block-cooperative, recompute full keys each round.
                unsigned int P = T16 << 16;
                for (int bit = 15; bit >= 0; --bit) {
                    if (t == 0) s_cnt = 0;
                    __syncthreads();
                    unsigned int C = P | (1u << bit);
                    int c = 0;
                    for (int n = t; n < N_RES; n += TPB) {
                        if (key16[n] == T16) {
                            float px = __ldg(ca + (row + n) * 3 + 0);
                            float py = __ldg(ca + (row + n) * 3 + 1);
                            float pz = __ldg(ca + (row + n) * 3 + 2);
                            float mm = __ldg(rmask + row + n);
                            c += (dist_key(cx, cy, cz, px, py, pz, mm) < C);
                        }
                    }
                    c = __reduce_add_sync(0xFFFFFFFFu, c);
                    if ((t & 31) == 0) atomicAdd(&s_cnt, c);
                    __syncthreads();
                    if (s_cnt < krem) P = C;
                    __syncthreads();
                }
                if (t == 0) {
                    int cb2 = 0;
                    for (int n = 0; n < N_RES; ++n) {
                        if (key16[n] == T16) {
                            float px = ca[(row + n) * 3 + 0];
                            float py = ca[(row + n) * 3 + 1];
                            float pz = ca[(row + n) * 3 + 2];
                            float mm = rmask[row + n];
                            cb2 += (dist_key(cx, cy, cz, px, py, pz, mm) < P);
                        }
                    }
                    int req = krem - cb2, seen = 0;
                    for (int n = 0; n < N_RES; ++n) {
                        if (key16[n] == T16) {
                            float px = ca[(row + n) * 3 + 0];
                            float py = ca[(row + n) * 3 + 1];
                            float pz = ca[(row + n) * 3 + 2];
                            float mm = rmask[row + n];
                            unsigned int x = dist_key(cx, cy, cz, px, py, pz, mm);
                            if (x > P) key16[n] = (unsigned short)0xFFFFu;
                            else if (x == P) {
                                ++seen;
                                if (seen > req) key16[n] = (unsigned short)0xFFFFu;
                            }
                        }
                    }
                }
            }
        }
    } else if (t == 0) {
        s_T16 = (kk >= N_RES) ? 0xFFFFu : 0u;   // all / none
    }
    __syncthreads();

    // ---- write both masks: streaming 128-bit stores (__stcs — outputs are
    //      never re-read; don't allocate them in L2).
    const unsigned int T16 = s_T16;
    const uint4* kv = reinterpret_cast<const uint4*>(key16);
    float4* o0 = reinterpret_cast<float4*>(out0 + row);
    float4* o1 = reinterpret_cast<float4*>(out1 + row);
    #pragma unroll 2
    for (int q = t; q < NU4; q += TPB) {
        uint4 v = kv[q];
        unsigned int xs[8] = {v.x & 0xFFFFu, v.x >> 16, v.y & 0xFFFFu, v.y >> 16,
                              v.z & 0xFFFFu, v.z >> 16, v.w & 0xFFFFu, v.w >> 16};
        float4 m0 = rm4[q * 2 + 0];
        float4 m1 = rm4[q * 2 + 1];
        float4 a0, a1, b0, b1;
        a0.x = (xs[0] <= T16) ? 0.0f : m0.x;
        a0.y = (xs[1] <= T16) ? 0.0f : m0.y;
        a0.z = (xs[2] <= T16) ? 0.0f : m0.z;
        a0.w = (xs[3] <= T16) ? 0.0f : m0.w;
        a1.x = (xs[4] <= T16) ? 0.0f : m1.x;
        a1.y = (xs[5] <= T16) ? 0.0f : m1.y;
        a1.z = (xs[6] <= T16) ? 0.0f : m1.z;
        a1.w = (xs[7] <= T16) ? 0.0f : m1.w;
        b0.x = (xs[0] <= T16) ? 32.0f : __fsub_rn(1.0f, m0.x);
        b0.y = (xs[1] <= T16) ? 32.0f : __fsub_rn(1.0f, m0.y);
        b0.z = (xs[2] <= T16) ? 32.0f : __fsub_rn(1.0f, m0.z);
        b0.w = (xs[3] <= T16) ? 32.0f : __fsub_rn(1.0f, m0.w);
        b1.x = (xs[4] <= T16) ? 32.0f : __fsub_rn(1.0f, m1.x);
        b1.y = (xs[5] <= T16) ? 32.0f : __fsub_rn(1.0f, m1.y);
        b1.z = (xs[6] <= T16) ? 32.0f : __fsub_rn(1.0f, m1.z);
        b1.w = (xs[7] <= T16) ? 32.0f : __fsub_rn(1.0f, m1.w);
        __stcs(&o0[q * 2 + 0], a0);
        __stcs(&o0[q * 2 + 1], a1);
        __stcs(&o1[q * 2 + 0], b0);
        __stcs(&o1[q * 2 + 1], b1);
    }
}

extern "C" void kernel_launch(void* const* d_in, const int* in_sizes, int n_in,
                              void* d_out, int out_size) {
    const float* ca    = (const float*)d_in[0];
    const float* rmask = (const float*)d_in[1];
    const float* apos  = (const float*)d_in[2];
    const float* amask = (const float*)d_in[3];
    const int*   topk  = (const int*)d_in[5];   // [ca, rmask, apos, amask, max_p, top_k]

    const int BN = in_sizes[1];          // B * N
    const int B  = BN / N_RES;
    const int A  = (B > 0) ? in_sizes[3] / B : 64;

    float* out0 = (float*)d_out;
    float* out1 = out0 + (size_t)BN;

    cudaFuncSetAttribute(spatial_mask_kernel,
                         cudaFuncAttributeMaxDynamicSharedMemorySize, SMEM_BYTES);
    spatial_mask_kernel<<<B, TPB, SMEM_BYTES>>>(ca, rmask, apos, amask, topk, A,
                                                out0, out1);
}

// round 16
// speedup vs baseline: 1.2299x; 1.1781x over previous
#include <cuda_runtime.h>
#include <stdint.h>

// Shape fixed for this dataset: B=512 rows, N=16384 residues/row, A atoms/row.
#define N_RES    16384
#define TPB      384
#define NG4      (N_RES / 4)     // 4096 build groups (4 residues each)
#define NU4      (N_RES / 8)     // 2048 uint4 groups of 8 key16s
#define HBINS    2048            // histogram on key bits 31..21
#define CAP      1024
// dynamic smem: key16 32KB | hist 8KB | cand_idx 4KB | cand_key 4KB = 48KB
#define SMEM_BYTES (32768 + 8192 + 4096 + 4096)

// Order-preserving float->uint transform (total order == IEEE float compare).
__device__ __forceinline__ unsigned int f2key(float f) {
    unsigned int u = __float_as_uint(f);
    return u ^ ((u & 0x80000000u) ? 0xFFFFFFFFu : 0x80000000u);
}

// Exact replica of reference arithmetic (RN, no FMA contraction).
__device__ __forceinline__ unsigned int dist_key(float cx, float cy, float cz,
                                                 float px, float py, float pz,
                                                 float m) {
    float dx = __fsub_rn(cx, px);
    float dy = __fsub_rn(cy, py);
    float dz = __fsub_rn(cz, pz);
    float ss = __fadd_rn(__fadd_rn(__fmul_rn(dx, dx), __fmul_rn(dy, dy)),
                         __fmul_rn(dz, dz));
    float d = __fsqrt_rn(__fadd_rn(ss, 1e-12f));
    d = __fadd_rn(d, __fmul_rn(__fsub_rn(1.0f, m), 1.0e10f));
    return f2key(d);
}

__device__ __forceinline__ void hist_add(unsigned int* hist, unsigned int bin) {
    unsigned int peers = __match_any_sync(0xFFFFFFFFu, bin);
    int leader = __ffs(peers) - 1;
    if ((threadIdx.x & 31) == leader) atomicAdd(&hist[bin], __popc(peers));
}

__global__ void __launch_bounds__(TPB, 4)
spatial_mask_kernel(const float* __restrict__ ca,      // [B, N, 3]
                    const float* __restrict__ rmask,   // [B, N]
                    const float* __restrict__ apos,    // [B, A, 3]
                    const float* __restrict__ amask,   // [B, A]
                    const int*   __restrict__ topk_ptr,
                    int A,
                    float* __restrict__ out0,          // [B, N]
                    float* __restrict__ out1)          // [B, N]
{
    extern __shared__ unsigned char sm[];
    unsigned short* key16    = reinterpret_cast<unsigned short*>(sm);        // [16384]
    unsigned int*   hist     = reinterpret_cast<unsigned int*>(sm + 32768);  // [2048]
    unsigned int*   cand_idx = reinterpret_cast<unsigned int*>(sm + 32768 + 8192);  // [1024]
    unsigned int*   cand_key = reinterpret_cast<unsigned int*>(sm + 32768 + 8192 + 4096); // [1024]

    __shared__ float s_cx, s_cy, s_cz;
    __shared__ int s_k;
    __shared__ unsigned int s_wsum[8];
    __shared__ unsigned int s_sub[32];
    __shared__ int s_b11, s_cb11;
    __shared__ unsigned int s_T16;
    __shared__ int s_cb, s_gsz, s_nc, s_cnt;

    const int b = blockIdx.x;
    const int t = threadIdx.x;
    const size_t row = (size_t)b * N_RES;

    for (int i = t; i < HBINS; i += TPB) hist[i] = 0;
    if (t < 32) s_sub[t] = 0;
    if (t == 32) s_nc = 0;
    if (t == 33) s_cnt = 0;
    if (t == 34) { s_b11 = 0; s_cb11 = 0; }

    // ---- centroid: strict sequential f32 sum in atom order.
    if (t == 0) {
        const float* ap = apos + (size_t)b * A * 3;
        const float* am = amask + (size_t)b * A;
        float sx = 0.f, sy = 0.f, sz = 0.f, smm = 0.f;
        #pragma unroll 4
        for (int a = 0; a < A; ++a) {
            sx  = __fadd_rn(sx,  ap[a * 3 + 0]);
            sy  = __fadd_rn(sy,  ap[a * 3 + 1]);
            sz  = __fadd_rn(sz,  ap[a * 3 + 2]);
            smm = __fadd_rn(smm, am[a]);
        }
        s_cx = __fdiv_rn(sx, smm);
        s_cy = __fdiv_rn(sy, smm);
        s_cz = __fdiv_rn(sz, smm);
        s_k  = *topk_ptr;
    }
    __syncthreads();
    const float cx = s_cx, cy = s_cy, cz = s_cz;
    const int kk = s_k;
    const bool normalK = (kk > 0 && kk < N_RES);

    // ---- build: distances -> key16 in SMEM + inline histogram.
    //      ca is single-use: evict-first streaming loads (__ldcs) to keep L2
    //      free for the rmask re-read in the write pass.
    const float4* ca4 = reinterpret_cast<const float4*>(ca + row * 3);
    const float4* rm4 = reinterpret_cast<const float4*>(rmask + row);
    uint2* key16v = reinterpret_cast<uint2*>(key16);
    #pragma unroll 4
    for (int g = t; g < NG4; g += TPB) {
        float4 v0 = __ldcs(&ca4[g * 3 + 0]);
        float4 v1 = __ldcs(&ca4[g * 3 + 1]);
        float4 v2 = __ldcs(&ca4[g * 3 + 2]);
        float4 m  = rm4[g];
        unsigned int k0 = dist_key(cx, cy, cz, v0.x, v0.y, v0.z, m.x);
        unsigned int k1 = dist_key(cx, cy, cz, v0.w, v1.x, v1.y, m.y);
        unsigned int k2 = dist_key(cx, cy, cz, v1.z, v1.w, v2.x, m.z);
        unsigned int k3 = dist_key(cx, cy, cz, v2.y, v2.z, v2.w, m.w);
        uint2 packed;
        packed.x = (k0 >> 16) | (k1 & 0xFFFF0000u);
        packed.y = (k2 >> 16) | (k3 & 0xFFFF0000u);
        key16v[g] = packed;
        if (normalK) {
            hist_add(hist, k0 >> 21);
            hist_add(hist, k1 >> 21);
            hist_add(hist, k2 >> 21);
            hist_add(hist, k3 >> 21);
        }
    }
    __syncthreads();

    if (normalK) {
        // ---- scan 2048-bin histogram: find 11-bit bin containing the k-th key
        {
            const int w = t >> 5, lane = t & 31;
            unsigned int hh[8];
            unsigned int local = 0, incl = 0;
            if (t < 256) {
                uint4 h0 = reinterpret_cast<uint4*>(hist)[t * 2];
                uint4 h1 = reinterpret_cast<uint4*>(hist)[t * 2 + 1];
                hh[0]=h0.x; hh[1]=h0.y; hh[2]=h0.z; hh[3]=h0.w;
                hh[4]=h1.x; hh[5]=h1.y; hh[6]=h1.z; hh[7]=h1.w;
                #pragma unroll
                for (int j = 0; j < 8; ++j) local += hh[j];
                incl = local;
                #pragma unroll
                for (int o = 1; o < 32; o <<= 1) {
                    unsigned int v = __shfl_up_sync(0xFFFFFFFFu, incl, o);
                    if (lane >= o) incl += v;
                }
                if (lane == 31) s_wsum[w] = incl;
            }
            __syncthreads();
            if (t < 256) {
                unsigned int pw = 0;
                for (int j = 0; j < w; ++j) pw += s_wsum[j];
                unsigned int pre = pw + incl - local;   // exclusive prefix
                if ((int)pre < kk && (int)(pre + local) >= kk) {
                    unsigned int cum = pre;
                    #pragma unroll
                    for (int j = 0; j < 8; ++j) {
                        if ((int)(cum + hh[j]) >= kk) { s_b11 = t * 8 + j; s_cb11 = (int)cum; break; }
                        cum += hh[j];
                    }
                }
            }
            __syncthreads();
        }

        // ---- sub-histogram (5 low bits of key16) within the chosen 11-bit bin
        {
            const unsigned int b11 = (unsigned int)s_b11;
            const uint4* kv = reinterpret_cast<const uint4*>(key16);
            #pragma unroll 2
            for (int q = t; q < NU4; q += TPB) {
                uint4 v = kv[q];
                unsigned int xs[8] = {v.x & 0xFFFFu, v.x >> 16, v.y & 0xFFFFu, v.y >> 16,
                                      v.z & 0xFFFFu, v.z >> 16, v.w & 0xFFFFu, v.w >> 16};
                #pragma unroll
                for (int j = 0; j < 8; ++j) {
                    bool p = ((xs[j] >> 5) == b11);
                    unsigned int act = __ballot_sync(0xFFFFFFFFu, p);
                    if (p) {
                        unsigned int sub = xs[j] & 31u;
                        unsigned int peers = __match_any_sync(act, sub);
                        int leader = __ffs(peers) - 1;
                        if ((t & 31) == leader) atomicAdd(&s_sub[sub], __popc(peers));
                    }
                }
            }
            __syncthreads();
            if (t == 0) {
                int cum = s_cb11;
                #pragma unroll
                for (int j = 0; j < 32; ++j) {
                    int h = (int)s_sub[j];
                    if (cum + h >= kk) {
                        s_T16 = ((unsigned int)s_b11 << 5) | (unsigned int)j;
                        s_cb = cum;
                        s_gsz = h;
                        break;
                    }
                    cum += h;
                }
            }
            __syncthreads();
        }

        const unsigned int T16 = s_T16;
        const int krem = kk - s_cb;
        const bool need_resolve = (krem < s_gsz);

        if (need_resolve) {
            // ---- compact candidates (key16 == T16)
            const uint4* kv = reinterpret_cast<const uint4*>(key16);
            #pragma unroll 2
            for (int q = t; q < NU4; q += TPB) {
                uint4 v = kv[q];
                unsigned int xs[8] = {v.x & 0xFFFFu, v.x >> 16, v.y & 0xFFFFu, v.y >> 16,
                                      v.z & 0xFFFFu, v.z >> 16, v.w & 0xFFFFu, v.w >> 16};
                #pragma unroll
                for (int j = 0; j < 8; ++j) {
                    if (xs[j] == T16) {
                        int pos = atomicAdd(&s_nc, 1);
                        if (pos < CAP) cand_idx[pos] = (unsigned int)(q * 8 + j);
                    }
                }
            }
            __syncthreads();
            const int nc = s_nc;

            if (nc <= CAP) {
                // ---- warp 0: recompute full keys for candidates, resolve low 16 bits
                if (t < 32) {
                    for (int i = t; i < nc; i += 32) {
                        int n = (int)cand_idx[i];
                        float px = __ldg(ca + (row + n) * 3 + 0);
                        float py = __ldg(ca + (row + n) * 3 + 1);
                        float pz = __ldg(ca + (row + n) * 3 + 2);
                        float m  = __ldg(rmask + row + n);
                        cand_key[i] = dist_key(cx, cy, cz, px, py, pz, m);
                    }
                    __syncwarp();
                    unsigned int P = T16 << 16;
                    for (int bit = 15; bit >= 0; --bit) {
                        unsigned int C = P | (1u << bit);
                        int c = 0;
                        for (int i = t; i < nc; i += 32) c += (cand_key[i] < C);
                        c = __reduce_add_sync(0xFFFFFFFFu, c);
                        if (c < krem) P = C;
                    }
                    int cb2 = 0;
                    for (int i = t; i < nc; i += 32) cb2 += (cand_key[i] < P);
                    cb2 = __reduce_add_sync(0xFFFFFFFFu, cb2);
                    const int req = krem - cb2;   // # of ==P keys to keep (by index)
                    for (int i = t; i < nc; i += 32) {
                        unsigned int x = cand_key[i];
                        bool sel;
                        if (x < P) sel = true;
                        else if (x > P) sel = false;
                        else {
                            int rk = 0;
                            unsigned int my = cand_idx[i];
                            for (int j = 0; j < nc; ++j)
                                rk += (cand_key[j] == P && cand_idx[j] < my);
                            sel = (rk < req);   // lowest-index ties kept (top_k stable)
                        }
                        if (!sel) key16[cand_idx[i]] = (unsigned short)0xFFFFu;
                    }
                }
            } else {
                // ---- fallback (cap overflow; effectively never taken): exact,
                //      block-cooperative, recompute full keys each round.
                unsigned int P = T16 << 16;
                for (int bit = 15; bit >= 0; --bit) {
                    if (t == 0) s_cnt = 0;
                    __syncthreads();
                    unsigned int C = P | (1u << bit);
                    int c = 0;
                    for (int n = t; n < N_RES; n += TPB) {
                        if (key16[n] == T16) {
                            float px = __ldg(ca + (row + n) * 3 + 0);
                            float py = __ldg(ca + (row + n) * 3 + 1);
                            float pz = __ldg(ca + (row + n) * 3 + 2);
                            float m  = __ldg(rmask + row + n);
                            c += (dist_key(cx, cy, cz, px, py, pz, m) < C);
                        }
                    }
                    c = __reduce_add_sync(0xFFFFFFFFu, c);
                    if ((t & 31) == 0) atomicAdd(&s_cnt, c);
                    __syncthreads();
                    if (s_cnt < krem) P = C;
                    __syncthreads();
                }
                if (t == 0) {
                    int cb2 = 0;
                    for (int n = 0; n < N_RES; ++n) {
                        if (key16[n] == T16) {
                            float px = ca[(row + n) * 3 + 0];
                            float py = ca[(row + n) * 3 + 1];
                            float pz = ca[(row + n) * 3 + 2];
                            float m  = rmask[row + n];
                            cb2 += (dist_key(cx, cy, cz, px, py, pz, m) < P);
                        }
                    }
                    int req = krem - cb2, seen = 0;
                    for (int n = 0; n < N_RES; ++n) {
                        if (key16[n] == T16) {
                            float px = ca[(row + n) * 3 + 0];
                            float py = ca[(row + n) * 3 + 1];
                            float pz = ca[(row + n) * 3 + 2];
                            float m  = rmask[row + n];
                            unsigned int x = dist_key(cx, cy, cz, px, py, pz, m);
                            if (x > P) key16[n] = (unsigned short)0xFFFFu;
                            else if (x == P) {
                                ++seen;
                                if (seen > req) key16[n] = (unsigned short)0xFFFFu;
                            }
                        }
                    }
                }
            }
        }
    } else if (t == 0) {
        s_T16 = (kk >= N_RES) ? 0xFFFFu : 0u;   // all / none
    }
    __syncthreads();

    // ---- write both masks: streaming 128-bit stores (__stcs — outputs are
    //      never re-read; don't allocate them in L2).
    const unsigned int T16 = s_T16;
    const uint4* kv = reinterpret_cast<const uint4*>(key16);
    float4* o0 = reinterpret_cast<float4*>(out0 + row);
    float4* o1 = reinterpret_cast<float4*>(out1 + row);
    #pragma unroll 2
    for (int q = t; q < NU4; q += TPB) {
        uint4 v = kv[q];
        unsigned int xs[8] = {v.x & 0xFFFFu, v.x >> 16, v.y & 0xFFFFu, v.y >> 16,
                              v.z & 0xFFFFu, v.z >> 16, v.w & 0xFFFFu, v.w >> 16};
        float4 m0 = rm4[q * 2 + 0];
        float4 m1 = rm4[q * 2 + 1];
        float4 a0, a1, b0, b1;
        a0.x = (xs[0] <= T16) ? 0.0f : m0.x;
        a0.y = (xs[1] <= T16) ? 0.0f : m0.y;
        a0.z = (xs[2] <= T16) ? 0.0f : m0.z;
        a0.w = (xs[3] <= T16) ? 0.0f : m0.w;
        a1.x = (xs[4] <= T16) ? 0.0f : m1.x;
        a1.y = (xs[5] <= T16) ? 0.0f : m1.y;
        a1.z = (xs[6] <= T16) ? 0.0f : m1.z;
        a1.w = (xs[7] <= T16) ? 0.0f : m1.w;
        b0.x = (xs[0] <= T16) ? 32.0f : __fsub_rn(1.0f, m0.x);
        b0.y = (xs[1] <= T16) ? 32.0f : __fsub_rn(1.0f, m0.y);
        b0.z = (xs[2] <= T16) ? 32.0f : __fsub_rn(1.0f, m0.z);
        b0.w = (xs[3] <= T16) ? 32.0f : __fsub_rn(1.0f, m0.w);
        b1.x = (xs[4] <= T16) ? 32.0f : __fsub_rn(1.0f, m1.x);
        b1.y = (xs[5] <= T16) ? 32.0f : __fsub_rn(1.0f, m1.y);
        b1.z = (xs[6] <= T16) ? 32.0f : __fsub_rn(1.0f, m1.z);
        b1.w = (xs[7] <= T16) ? 32.0f : __fsub_rn(1.0f, m1.w);
        __stcs(&o0[q * 2 + 0], a0);
        __stcs(&o0[q * 2 + 1], a1);
        __stcs(&o1[q * 2 + 0], b0);
        __stcs(&o1[q * 2 + 1], b1);
    }
}

extern "C" void kernel_launch(void* const* d_in, const int* in_sizes, int n_in,
                              void* d_out, int out_size) {
    const float* ca    = (const float*)d_in[0];
    const float* rmask = (const float*)d_in[1];
    const float* apos  = (const float*)d_in[2];
    const float* amask = (const float*)d_in[3];
    const int*   topk  = (const int*)d_in[5];   // [ca, rmask, apos, amask, max_p, top_k]

    const int BN = in_sizes[1];          // B * N
    const int B  = BN / N_RES;
    const int A  = (B > 0) ? in_sizes[3] / B : 64;

    float* out0 = (float*)d_out;
    float* out1 = out0 + (size_t)BN;

    cudaFuncSetAttribute(spatial_mask_kernel,
                         cudaFuncAttributeMaxDynamicSharedMemorySize, SMEM_BYTES);
    spatial_mask_kernel<<<B, TPB, SMEM_BYTES>>>(ca, rmask, apos, amask, topk, A,
                                                out0, out1);
}

// round 17
// speedup vs baseline: 1.3296x; 1.0811x over previous
#include <cuda_runtime.h>
#include <stdint.h>

// Shape fixed for this dataset: B=512 rows, N=16384 residues/row, A atoms/row.
#define N_RES    16384
#define TPB      384
#define NWARP    (TPB / 32)      // 12
#define NG4      (N_RES / 4)     // 4096 build groups (4 residues each)
#define NU4      (N_RES / 8)     // 2048 uint4 groups of 8 key16s
#define HBINS    2048            // histogram on key bits 31..21
#define CAP      1024
// dynamic smem: key16 32KB | hist 8KB | cand_idx 4KB | cand_key 4KB = 48KB
#define SMEM_BYTES (32768 + 8192 + 4096 + 4096)

// Order-preserving float->uint transform (total order == IEEE float compare).
__device__ __forceinline__ unsigned int f2key(float f) {
    unsigned int u = __float_as_uint(f);
    return u ^ ((u & 0x80000000u) ? 0xFFFFFFFFu : 0x80000000u);
}

// Exact replica of reference arithmetic (RN, no FMA contraction).
__device__ __forceinline__ unsigned int dist_key(float cx, float cy, float cz,
                                                 float px, float py, float pz,
                                                 float m) {
    float dx = __fsub_rn(cx, px);
    float dy = __fsub_rn(cy, py);
    float dz = __fsub_rn(cz, pz);
    float ss = __fadd_rn(__fadd_rn(__fmul_rn(dx, dx), __fmul_rn(dy, dy)),
                         __fmul_rn(dz, dz));
    float d = __fsqrt_rn(__fadd_rn(ss, 1e-12f));
    d = __fadd_rn(d, __fmul_rn(__fsub_rn(1.0f, m), 1.0e10f));
    return f2key(d);
}

__device__ __forceinline__ void hist_add(unsigned int* hist, unsigned int bin) {
    unsigned int peers = __match_any_sync(0xFFFFFFFFu, bin);
    int leader = __ffs(peers) - 1;
    if ((threadIdx.x & 31) == leader) atomicAdd(&hist[bin], __popc(peers));
}

__global__ void __launch_bounds__(TPB, 4)
spatial_mask_kernel(const float* __restrict__ ca,      // [B, N, 3]
                    const float* __restrict__ rmask,   // [B, N]
                    const float* __restrict__ apos,    // [B, A, 3]
                    const float* __restrict__ amask,   // [B, A]
                    const int*   __restrict__ topk_ptr,
                    int A,
                    float* __restrict__ out0,          // [B, N]
                    float* __restrict__ out1)          // [B, N]
{
    extern __shared__ unsigned char sm[];
    unsigned short* key16    = reinterpret_cast<unsigned short*>(sm);        // [16384]
    unsigned int*   hist     = reinterpret_cast<unsigned int*>(sm + 32768);  // [2048]
    unsigned int*   cand_idx = reinterpret_cast<unsigned int*>(sm + 32768 + 8192);  // [1024]
    unsigned int*   cand_key = reinterpret_cast<unsigned int*>(sm + 32768 + 8192 + 4096); // [1024]

    __shared__ float s_cx, s_cy, s_cz;
    __shared__ int s_k;
    __shared__ unsigned int s_wsum[8];
    __shared__ unsigned int s_subw[NWARP][32];   // warp-private sub-hist banks
    __shared__ int s_b11, s_cb11;
    __shared__ unsigned int s_T16;
    __shared__ int s_cb, s_gsz, s_nc, s_cnt;

    const int b = blockIdx.x;
    const int t = threadIdx.x;
    const int wid = t >> 5;
    const int lane = t & 31;
    const size_t row = (size_t)b * N_RES;

    for (int i = t; i < HBINS; i += TPB) hist[i] = 0;
    s_subw[wid][lane] = 0;                      // TPB == NWARP*32: full init
    if (t == 32) s_nc = 0;
    if (t == 33) s_cnt = 0;
    if (t == 34) { s_b11 = 0; s_cb11 = 0; }

    // ---- centroid: strict sequential f32 sum in atom order.
    if (t == 0) {
        const float* ap = apos + (size_t)b * A * 3;
        const float* am = amask + (size_t)b * A;
        float sx = 0.f, sy = 0.f, sz = 0.f, smm = 0.f;
        #pragma unroll 4
        for (int a = 0; a < A; ++a) {
            sx  = __fadd_rn(sx,  ap[a * 3 + 0]);
            sy  = __fadd_rn(sy,  ap[a * 3 + 1]);
            sz  = __fadd_rn(sz,  ap[a * 3 + 2]);
            smm = __fadd_rn(smm, am[a]);
        }
        s_cx = __fdiv_rn(sx, smm);
        s_cy = __fdiv_rn(sy, smm);
        s_cz = __fdiv_rn(sz, smm);
        s_k  = *topk_ptr;
    }
    __syncthreads();
    const float cx = s_cx, cy = s_cy, cz = s_cz;
    const int kk = s_k;
    const bool normalK = (kk > 0 && kk < N_RES);

    // ---- build: distances -> key16 in SMEM + inline histogram.
    //      ca is single-use: evict-first streaming loads (__ldcs).
    const float4* ca4 = reinterpret_cast<const float4*>(ca + row * 3);
    const float4* rm4 = reinterpret_cast<const float4*>(rmask + row);
    uint2* key16v = reinterpret_cast<uint2*>(key16);
    #pragma unroll 4
    for (int g = t; g < NG4; g += TPB) {
        float4 v0 = __ldcs(&ca4[g * 3 + 0]);
        float4 v1 = __ldcs(&ca4[g * 3 + 1]);
        float4 v2 = __ldcs(&ca4[g * 3 + 2]);
        float4 m  = rm4[g];
        unsigned int k0 = dist_key(cx, cy, cz, v0.x, v0.y, v0.z, m.x);
        unsigned int k1 = dist_key(cx, cy, cz, v0.w, v1.x, v1.y, m.y);
        unsigned int k2 = dist_key(cx, cy, cz, v1.z, v1.w, v2.x, m.z);
        unsigned int k3 = dist_key(cx, cy, cz, v2.y, v2.z, v2.w, m.w);
        uint2 packed;
        packed.x = (k0 >> 16) | (k1 & 0xFFFF0000u);
        packed.y = (k2 >> 16) | (k3 & 0xFFFF0000u);
        key16v[g] = packed;
        if (normalK) {
            hist_add(hist, k0 >> 21);
            hist_add(hist, k1 >> 21);
            hist_add(hist, k2 >> 21);
            hist_add(hist, k3 >> 21);
        }
    }
    __syncthreads();

    if (normalK) {
        // ---- scan 2048-bin histogram: find 11-bit bin containing the k-th key
        {
            const int w = t >> 5;
            unsigned int hh[8];
            unsigned int local = 0, incl = 0;
            if (t < 256) {
                uint4 h0 = reinterpret_cast<uint4*>(hist)[t * 2];
                uint4 h1 = reinterpret_cast<uint4*>(hist)[t * 2 + 1];
                hh[0]=h0.x; hh[1]=h0.y; hh[2]=h0.z; hh[3]=h0.w;
                hh[4]=h1.x; hh[5]=h1.y; hh[6]=h1.z; hh[7]=h1.w;
                #pragma unroll
                for (int j = 0; j < 8; ++j) local += hh[j];
                incl = local;
                #pragma unroll
                for (int o = 1; o < 32; o <<= 1) {
                    unsigned int v = __shfl_up_sync(0xFFFFFFFFu, incl, o);
                    if (lane >= o) incl += v;
                }
                if (lane == 31) s_wsum[w] = incl;
            }
            __syncthreads();
            if (t < 256) {
                unsigned int pw = 0;
                for (int j = 0; j < w; ++j) pw += s_wsum[j];
                unsigned int pre = pw + incl - local;   // exclusive prefix
                if ((int)pre < kk && (int)(pre + local) >= kk) {
                    unsigned int cum = pre;
                    #pragma unroll
                    for (int j = 0; j < 8; ++j) {
                        if ((int)(cum + hh[j]) >= kk) { s_b11 = t * 8 + j; s_cb11 = (int)cum; break; }
                        cum += hh[j];
                    }
                }
            }
            __syncthreads();
        }

        // ---- sub-histogram (5 low bits of key16) within the chosen 11-bit bin.
        //      Warp-private banks: plain predicated atomics, zero cross-warp
        //      contention, no ballot/match machinery in the 16K loop.
        {
            const unsigned int b11 = (unsigned int)s_b11;
            unsigned int* mysub = s_subw[wid];
            const uint4* kv = reinterpret_cast<const uint4*>(key16);
            #pragma unroll 2
            for (int q = t; q < NU4; q += TPB) {
                uint4 v = kv[q];
                unsigned int xs[8] = {v.x & 0xFFFFu, v.x >> 16, v.y & 0xFFFFu, v.y >> 16,
                                      v.z & 0xFFFFu, v.z >> 16, v.w & 0xFFFFu, v.w >> 16};
                #pragma unroll
                for (int j = 0; j < 8; ++j) {
                    if ((xs[j] >> 5) == b11)
                        atomicAdd(&mysub[xs[j] & 31u], 1u);
                }
            }
            __syncthreads();
            if (t == 0) {
                int cum = s_cb11;
                #pragma unroll
                for (int j = 0; j < 32; ++j) {
                    int h = 0;
                    #pragma unroll
                    for (int w2 = 0; w2 < NWARP; ++w2) h += (int)s_subw[w2][j];
                    if (cum + h >= kk) {
                        s_T16 = ((unsigned int)s_b11 << 5) | (unsigned int)j;
                        s_cb = cum;
                        s_gsz = h;
                        break;
                    }
                    cum += h;
                }
            }
            __syncthreads();
        }

        const unsigned int T16 = s_T16;
        const int krem = kk - s_cb;
        const bool need_resolve = (krem < s_gsz);

        if (need_resolve) {
            // ---- compact candidates (key16 == T16) — group is tiny, plain atomics.
            const uint4* kv = reinterpret_cast<const uint4*>(key16);
            #pragma unroll 2
            for (int q = t; q < NU4; q += TPB) {
                uint4 v = kv[q];
                unsigned int xs[8] = {v.x & 0xFFFFu, v.x >> 16, v.y & 0xFFFFu, v.y >> 16,
                                      v.z & 0xFFFFu, v.z >> 16, v.w & 0xFFFFu, v.w >> 16};
                #pragma unroll
                for (int j = 0; j < 8; ++j) {
                    if (xs[j] == T16) {
                        int pos = atomicAdd(&s_nc, 1);
                        if (pos < CAP) cand_idx[pos] = (unsigned int)(q * 8 + j);
                    }
                }
            }
            __syncthreads();
            const int nc = s_nc;

            if (nc <= CAP) {
                // ---- warp 0: recompute full keys for candidates, resolve low 16 bits
                if (t < 32) {
                    for (int i = t; i < nc; i += 32) {
                        int n = (int)cand_idx[i];
                        float px = __ldg(ca + (row + n) * 3 + 0);
                        float py = __ldg(ca + (row + n) * 3 + 1);
                        float pz = __ldg(ca + (row + n) * 3 + 2);
                        float m  = __ldg(rmask + row + n);
                        cand_key[i] = dist_key(cx, cy, cz, px, py, pz, m);
                    }
                    __syncwarp();
                    unsigned int P = T16 << 16;
                    for (int bit = 15; bit >= 0; --bit) {
                        unsigned int C = P | (1u << bit);
                        int c = 0;
                        for (int i = t; i < nc; i += 32) c += (cand_key[i] < C);
                        c = __reduce_add_sync(0xFFFFFFFFu, c);
                        if (c < krem) P = C;
                    }
                    int cb2 = 0;
                    for (int i = t; i < nc; i += 32) cb2 += (cand_key[i] < P);
                    cb2 = __reduce_add_sync(0xFFFFFFFFu, cb2);
                    const int req = krem - cb2;   // # of ==P keys to keep (by index)
                    for (int i = t; i < nc; i += 32) {
                        unsigned int x = cand_key[i];
                        bool sel;
                        if (x < P) sel = true;
                        else if (x > P) sel = false;
                        else {
                            int rk = 0;
                            unsigned int my = cand_idx[i];
                            for (int j = 0; j < nc; ++j)
                                rk += (cand_key[j] == P && cand_idx[j] < my);
                            sel = (rk < req);   // lowest-index ties kept (top_k stable)
                        }
                        if (!sel) key16[cand_idx[i]] = (unsigned short)0xFFFFu;
                    }
                }
            } else {
                // ---- fallback (cap overflow; effectively never taken): exact,
                //      block-cooperative, recompute full keys each round.
                unsigned int P = T16 << 16;
                for (int bit = 15; bit >= 0; --bit) {
                    if (t == 0) s_cnt = 0;
                    __syncthreads();
                    unsigned int C = P | (1u << bit);
                    int c = 0;
                    for (int n = t; n < N_RES; n += TPB) {
                        if (key16[n] == T16) {
                            float px = __ldg(ca + (row + n) * 3 + 0);
                            float py = __ldg(ca + (row + n) * 3 + 1);
                            float pz = __ldg(ca + (row + n) * 3 + 2);
                            float m  = __ldg(rmask + row + n);
                            c += (dist_key(cx, cy, cz, px, py, pz, m) < C);
                        }
                    }
                    c = __reduce_add_sync(0xFFFFFFFFu, c);
                    if ((t & 31) == 0) atomicAdd(&s_cnt, c);
                    __syncthreads();
                    if (s_cnt < krem) P = C;
                    __syncthreads();
                }
                if (t == 0) {
                    int cb2 = 0;
                    for (int n = 0; n < N_RES; ++n) {
                        if (key16[n] == T16) {
                            float px = ca[(row + n) * 3 + 0];
                            float py = ca[(row + n) * 3 + 1];
                            float pz = ca[(row + n) * 3 + 2];
                            float m  = rmask[row + n];
                            cb2 += (dist_key(cx, cy, cz, px, py, pz, m) < P);
                        }
                    }
                    int req = krem - cb2, seen = 0;
                    for (int n = 0; n < N_RES; ++n) {
                        if (key16[n] == T16) {
                            float px = ca[(row + n) * 3 + 0];
                            float py = ca[(row + n) * 3 + 1];
                            float pz = ca[(row + n) * 3 + 2];
                            float m  = rmask[row + n];
                            unsigned int x = dist_key(cx, cy, cz, px, py, pz, m);
                            if (x > P) key16[n] = (unsigned short)0xFFFFu;
                            else if (x == P) {
                                ++seen;
                                if (seen > req) key16[n] = (unsigned short)0xFFFFu;
                            }
                        }
                    }
                }
            }
        }
    } else if (t == 0) {
        s_T16 = (kk >= N_RES) ? 0xFFFFu : 0u;   // all / none
    }
    __syncthreads();

    // ---- write both masks: streaming 128-bit stores (__stcs — outputs are
    //      never re-read; don't allocate them in L2).
    const unsigned int T16 = s_T16;
    const uint4* kv = reinterpret_cast<const uint4*>(key16);
    float4* o0 = reinterpret_cast<float4*>(out0 + row);
    float4* o1 = reinterpret_cast<float4*>(out1 + row);
    #pragma unroll 2
    for (int q = t; q < NU4; q += TPB) {
        uint4 v = kv[q];
        unsigned int xs[8] = {v.x & 0xFFFFu, v.x >> 16, v.y & 0xFFFFu, v.y >> 16,
                              v.z & 0xFFFFu, v.z >> 16, v.w & 0xFFFFu, v.w >> 16};
        float4 m0 = rm4[q * 2 + 0];
        float4 m1 = rm4[q * 2 + 1];
        float4 a0, a1, b0, b1;
        a0.x = (xs[0] <= T16) ? 0.0f : m0.x;
        a0.y = (xs[1] <= T16) ? 0.0f : m0.y;
        a0.z = (xs[2] <= T16) ? 0.0f : m0.z;
        a0.w = (xs[3] <= T16) ? 0.0f : m0.w;
        a1.x = (xs[4] <= T16) ? 0.0f : m1.x;
        a1.y = (xs[5] <= T16) ? 0.0f : m1.y;
        a1.z = (xs[6] <= T16) ? 0.0f : m1.z;
        a1.w = (xs[7] <= T16) ? 0.0f : m1.w;
        b0.x = (xs[0] <= T16) ? 32.0f : __fsub_rn(1.0f, m0.x);
        b0.y = (xs[1] <= T16) ? 32.0f : __fsub_rn(1.0f, m0.y);
        b0.z = (xs[2] <= T16) ? 32.0f : __fsub_rn(1.0f, m0.z);
        b0.w = (xs[3] <= T16) ? 32.0f : __fsub_rn(1.0f, m0.w);
        b1.x = (xs[4] <= T16) ? 32.0f : __fsub_rn(1.0f, m1.x);
        b1.y = (xs[5] <= T16) ? 32.0f : __fsub_rn(1.0f, m1.y);
        b1.z = (xs[6] <= T16) ? 32.0f : __fsub_rn(1.0f, m1.z);
        b1.w = (xs[7] <= T16) ? 32.0f : __fsub_rn(1.0f, m1.w);
        __stcs(&o0[q * 2 + 0], a0);
        __stcs(&o0[q * 2 + 1], a1);
        __stcs(&o1[q * 2 + 0], b0);
        __stcs(&o1[q * 2 + 1], b1);
    }
}

extern "C" void kernel_launch(void* const* d_in, const int* in_sizes, int n_in,
                              void* d_out, int out_size) {
    const float* ca    = (const float*)d_in[0];
    const float* rmask = (const float*)d_in[1];
    const float* apos  = (const float*)d_in[2];
    const float* amask = (const float*)d_in[3];
    const int*   topk  = (const int*)d_in[5];   // [ca, rmask, apos, amask, max_p, top_k]

    const int BN = in_sizes[1];          // B * N
    const int B  = BN / N_RES;
    const int A  = (B > 0) ? in_sizes[3] / B : 64;

    float* out0 = (float*)d_out;
    float* out1 = out0 + (size_t)BN;

    cudaFuncSetAttribute(spatial_mask_kernel,
                         cudaFuncAttributeMaxDynamicSharedMemorySize, SMEM_BYTES);
    spatial_mask_kernel<<<B, TPB, SMEM_BYTES>>>(ca, rmask, apos, amask, topk, A,
                                                out0, out1);
}